// round 11
// baseline (speedup 1.0000x reference)
#include <cuda_runtime.h>
#include <cuda_fp16.h>
#include <cstdint>

#define THREADS 256
#define CTA_M   64
#define HROW    128                       // H row stride in words (512B rows)
#define XSLOTW  2048                      // X slot: 64 rows x 32 words (8KB), 4 slots alias H
#define WOFFW   8192
#define WSLOTW  4096                      // W slot: 256 rows x 16 words (16KB), 3 slots
#define SMEM_WORDS (WOFFW + 3 * WSLOTW)   // 20480
#define SMEM_BYTES (SMEM_WORDS * 4)       // 81920 (2 CTAs/SM; RF-limited to 2 anyway)

// pre-transposed fp16 weights, K-major: Wt[n][k]
__device__ __half g_W1t[256 * 512];
__device__ __half g_W2t[256 * 256];
__device__ __half g_W3t[128 * 256];

__device__ __forceinline__ uint32_t smem_u32(const void* p) {
    uint32_t a;
    asm("{ .reg .u64 t; cvta.to.shared.u64 t, %1; cvt.u32.u64 %0, t; }" : "=r"(a) : "l"(p));
    return a;
}
__device__ __forceinline__ float softplus_f(float x) {
    return (x > 20.0f) ? x : __logf(1.0f + __expf(x));
}
__device__ __forceinline__ uint32_t pack_h2(float lo, float hi) {
    __half2 h = __halves2half2(__float2half_rn(lo), __float2half_rn(hi));
    return *(uint32_t*)&h;
}
__device__ __forceinline__ void mma16(float* c, uint32_t a0, uint32_t a1,
                                      uint32_t a2, uint32_t a3,
                                      uint32_t b0, uint32_t b1) {
    asm volatile(
        "mma.sync.aligned.m16n8k16.row.col.f32.f16.f16.f32 "
        "{%0,%1,%2,%3}, {%4,%5,%6,%7}, {%8,%9}, {%0,%1,%2,%3};\n"
        : "+f"(c[0]), "+f"(c[1]), "+f"(c[2]), "+f"(c[3])
        : "r"(a0), "r"(a1), "r"(a2), "r"(a3), "r"(b0), "r"(b1));
}
__device__ __forceinline__ void ldsm4(uint32_t* r, uint32_t addr) {
    asm volatile("ldmatrix.sync.aligned.m8n8.x4.shared.b16 {%0,%1,%2,%3}, [%4];"
        : "=r"(r[0]), "=r"(r[1]), "=r"(r[2]), "=r"(r[3]) : "r"(addr));
}
__device__ __forceinline__ void cp16(uint32_t dst, const void* src) {
    asm volatile("cp.async.cg.shared.global [%0], [%1], 16;" :: "r"(dst), "l"(src) : "memory");
}
#define CP_COMMIT() asm volatile("cp.async.commit_group;" ::: "memory")
#define CP_WAIT1()  asm volatile("cp.async.wait_group 1;" ::: "memory")
#define CP_WAIT0()  asm volatile("cp.async.wait_group 0;" ::: "memory")

// ---- GEMM over one 32-K chunk. A: 64 rows, ^(row&7) swizzle (8 units/row),
// unit base aub. B: W slot, 64B rows, ^((row>>1)&3) swizzle (4 units/row).
template <int NTP>
__device__ __forceinline__ void gemm32(float acc[4][2 * NTP][4],
                                       uint32_t aBase, int arowB, int aub,
                                       uint32_t bRow, int lane) {
    int rw = lane & 7;
    int duA = (lane >> 4) & 1;
    int duB = (lane >> 3) & 1;
    int sB = (rw >> 1) & 3;
    uint32_t aL = aBase + (uint32_t)((((lane >> 3) & 1) * 8 + rw) * arowB);

    // all B upfront (2 gi x NTP), single-gi A buffer
    uint32_t b[2][NTP][4];
#pragma unroll
    for (int gi = 0; gi < 2; gi++) {
        uint32_t uB = (uint32_t)(((2 * gi + duB) ^ sB) << 4);
#pragma unroll
        for (int ntp = 0; ntp < NTP; ntp++)
            ldsm4(b[gi][ntp], bRow + ntp * (16 * 64) + uB);
    }
    uint32_t a[4][4];
#pragma unroll
    for (int gi = 0; gi < 2; gi++) {
        uint32_t uA = (uint32_t)((aub + 2 * gi + duA) ^ rw) << 4;
#pragma unroll
        for (int mt = 0; mt < 4; mt++)
            ldsm4(a[mt], aL + mt * 16 * arowB + uA);
#pragma unroll
        for (int ntp = 0; ntp < NTP; ntp++) {
#pragma unroll
            for (int mt = 0; mt < 4; mt++) {
                mma16(acc[mt][2 * ntp],     a[mt][0], a[mt][1], a[mt][2], a[mt][3],
                      b[gi][ntp][0], b[gi][ntp][1]);
                mma16(acc[mt][2 * ntp + 1], a[mt][0], a[mt][1], a[mt][2], a[mt][3],
                      b[gi][ntp][2], b[gi][ntp][3]);
            }
        }
    }
}

// ---- X staging (64-K window = 2 chunks), split LDG / STS ----
__device__ __forceinline__ const float* x_src(int w, long e0,
                                              const float* __restrict__ src,
                                              const float* __restrict__ dstp,
                                              const float* __restrict__ ea,
                                              const float* __restrict__ u,
                                              const void* __restrict__ batch,
                                              int b64, int row) {
    int seg = w >> 1;
    if (seg == 0) return src  + (e0 + row) * 128;
    if (seg == 1) return dstp + (e0 + row) * 128;
    if (seg == 2) return ea   + (e0 + row) * 128;
    long bi = b64 ? (long)((const long long*)batch)[e0 + row]
                  : (long)((const int*)batch)[e0 + row];
    return u + bi * 128;
}
__device__ __forceinline__ void x_ldg(float4 xv[4], const float* p, int w, int tid) {
    int q = tid & 3;
    int off = ((w & 1) * 64) + q * 16;
    xv[0] = *(const float4*)(p + off);
    xv[1] = *(const float4*)(p + off + 4);
    xv[2] = *(const float4*)(p + off + 8);
    xv[3] = *(const float4*)(p + off + 12);
}
__device__ __forceinline__ void x_sts(uint32_t* x, const float4 xv[4], int tid) {
    int row = tid >> 2, q = tid & 3;
    uint4 o1 = make_uint4(pack_h2(xv[0].x, xv[0].y), pack_h2(xv[0].z, xv[0].w),
                          pack_h2(xv[1].x, xv[1].y), pack_h2(xv[1].z, xv[1].w));
    uint4 o2 = make_uint4(pack_h2(xv[2].x, xv[2].y), pack_h2(xv[2].z, xv[2].w),
                          pack_h2(xv[3].x, xv[3].y), pack_h2(xv[3].z, xv[3].w));
    int rm = row & 7;
    *(uint4*)(x + row * 32 + (((2 * q) ^ rm) << 2)) = o1;
    *(uint4*)(x + row * 32 + (((2 * q + 1) ^ rm) << 2)) = o2;
}

// ---- W staging: one 32-K chunk via cp.async, 64B rows, 4-unit swizzle ----
template <int NROWS, int KFULL>
__device__ __forceinline__ void stage_w(uint32_t slot_byte, const __half* __restrict__ Wt,
                                        int kc, int tid) {
#pragma unroll
    for (int it = 0; it < (NROWS * 4) / THREADS; it++) {
        int task = tid + it * THREADS;
        int row = task >> 2, q = task & 3;
        uint32_t dst = slot_byte + (uint32_t)(row * 64 + (((q ^ ((row >> 1) & 3))) << 4));
        cp16(dst, Wt + (long)row * KFULL + kc * 32 + q * 8);
    }
}

// ---- epilogue layers 1/2: bias + softplus -> half2 into H ----
template <int NT>
__device__ __forceinline__ void epi_h(float acc[4][NT][4], uint32_t* smw,
                                      const float* __restrict__ bias,
                                      int n0, int g, int t) {
#pragma unroll
    for (int nt = 0; nt < NT; nt++) {
        int c = n0 + nt * 8 + 2 * t;
        float bb0 = __ldg(bias + c);
        float bb1 = __ldg(bias + c + 1);
        int uu = (n0 >> 3) + nt;
        int w = ((uu ^ g) << 2) + t;
#pragma unroll
        for (int mt = 0; mt < 4; mt++) {
            int r = mt * 16 + g;
            smw[r * HROW + w] =
                pack_h2(softplus_f(acc[mt][nt][0] + bb0), softplus_f(acc[mt][nt][1] + bb1));
            smw[(r + 8) * HROW + w] =
                pack_h2(softplus_f(acc[mt][nt][2] + bb0), softplus_f(acc[mt][nt][3] + bb1));
        }
    }
}

// ---- prepass: W [K][N] -> Wt [N][K] fp16 ----
__global__ void prep_w(const float* __restrict__ W, __half* __restrict__ Wt,
                       int K, int N) {
    __shared__ float tile[32][33];
    int kb = blockIdx.x * 32, nb = blockIdx.y * 32;
    int tx = threadIdx.x, ty = threadIdx.y;
    for (int i = ty; i < 32; i += 8)
        tile[i][tx] = W[(long)(kb + i) * N + nb + tx];
    __syncthreads();
    for (int i = ty; i < 32; i += 8)
        Wt[(long)(nb + i) * K + kb + tx] = __float2half_rn(tile[tx][i]);
}

__global__ void __launch_bounds__(THREADS, 2)
edge_mlp_v11(const float* __restrict__ src, const float* __restrict__ dstp,
             const float* __restrict__ ea, const float* __restrict__ u,
             const void* __restrict__ batch,
             const float* __restrict__ b1, const float* __restrict__ b2,
             const float* __restrict__ b3,
             float* __restrict__ out) {
    extern __shared__ uint32_t smw[];
    uint32_t sbyte = smem_u32(smw);

    int tid = threadIdx.x;
    int wid = tid >> 5;
    int lane = tid & 31;
    int g = lane >> 2;
    int t = lane & 3;
    int n0 = wid * 32;
    int n3 = wid * 16;
    long e0 = (long)blockIdx.x * CTA_M;

    // lane-resolved B row byte offsets (row = n + 8*((lane>>4)&1) + (lane&7), 64B rows)
    uint32_t rowoff12 = (uint32_t)((n0 + ((lane >> 4) & 1) * 8 + (lane & 7)) * 64);
    uint32_t rowoff3  = (uint32_t)((n3 + ((lane >> 4) & 1) * 8 + (lane & 7)) * 64);
    uint32_t wBase = sbyte + WOFFW * 4;

    __shared__ int b64s;
    if (tid == 0) {
        const long long* p = (const long long*)batch;
        int f = 1;
        for (int i = 0; i < 16; i++) { long long v = p[i]; if (v < 0 || v >= 64) f = 0; }
        b64s = f;
    }
    __syncthreads();
    int b64 = b64s;

    float acc[4][4][4];
#pragma unroll
    for (int a = 0; a < 4; a++)
#pragma unroll
        for (int b = 0; b < 4; b++)
#pragma unroll
            for (int c = 0; c < 4; c++) acc[a][b][c] = 0.0f;

    // ---- prolog: X window 0 -> slot 0; W1 chunks 0,1 -> slots 0,1 ----
    {
        float4 xv[4];
        x_ldg(xv, x_src(0, e0, src, dstp, ea, u, batch, b64, tid >> 2), 0, tid);
        stage_w<256, 512>(wBase, g_W1t, 0, tid);
        CP_COMMIT();
        stage_w<256, 512>(wBase + WSLOTW * 4, g_W1t, 1, tid);
        CP_COMMIT();
        x_sts(smw, xv, tid);
    }
    __syncthreads();

    // ============== Layer 1: 16 chunks of K=32 ==============
#pragma unroll 1
    for (int c = 0; c < 16; c++) {
        CP_WAIT1();
        __syncthreads();
        float4 xv[4];
        bool dox = ((c & 1) == 0) && (c <= 12);
        int wnext = (c >> 1) + 1;
        if (dox)
            x_ldg(xv, x_src(wnext, e0, src, dstp, ea, u, batch, b64, tid >> 2), wnext, tid);
        uint32_t stSlot = wBase + (uint32_t)(((c + 2) % 3) * (WSLOTW * 4));
        if (c + 2 < 16) stage_w<256, 512>(stSlot, g_W1t, c + 2, tid);
        else            stage_w<256, 256>(stSlot, g_W2t, c - 14, tid);
        CP_COMMIT();
        uint32_t bRow = wBase + (uint32_t)((c % 3) * (WSLOTW * 4)) + rowoff12;
        gemm32<2>(acc, sbyte + ((c >> 1) & 3) * (XSLOTW * 4), 128, 4 * (c & 1), bRow, lane);
        if (dox) x_sts(smw + (wnext & 3) * XSLOTW, xv, tid);
    }
    __syncthreads();                      // all gemm/X reads done
    epi_h<4>(acc, smw, b1, n0, g, t);
    __syncthreads();                      // publish H1

    // ============== Layer 2: 8 chunks of K=32, A = H ==============
#pragma unroll
    for (int a = 0; a < 4; a++)
#pragma unroll
        for (int b = 0; b < 4; b++)
#pragma unroll
            for (int c = 0; c < 4; c++) acc[a][b][c] = 0.0f;
#pragma unroll 1
    for (int j = 0; j < 8; j++) {
        int gch = 16 + j;
        CP_WAIT1();
        __syncthreads();
        uint32_t stSlot = wBase + (uint32_t)(((gch + 2) % 3) * (WSLOTW * 4));
        if (j + 2 < 8) stage_w<256, 256>(stSlot, g_W2t, j + 2, tid);
        else           stage_w<128, 256>(stSlot, g_W3t, j - 6, tid);
        CP_COMMIT();
        uint32_t bRow = wBase + (uint32_t)((gch % 3) * (WSLOTW * 4)) + rowoff12;
        gemm32<2>(acc, sbyte, 512, 4 * j, bRow, lane);
    }
    __syncthreads();                      // all H1 reads done
    epi_h<4>(acc, smw, b2, n0, g, t);
    __syncthreads();                      // publish H2

    // ============== Layer 3: 8 chunks of K=32, A = H, N=128 ==============
    float acc3[4][2][4];
#pragma unroll
    for (int a = 0; a < 4; a++)
#pragma unroll
        for (int b = 0; b < 2; b++)
#pragma unroll
            for (int c = 0; c < 4; c++) acc3[a][b][c] = 0.0f;
#pragma unroll 1
    for (int j = 0; j < 8; j++) {
        int gch = 24 + j;
        if (j >= 6) CP_WAIT0(); else CP_WAIT1();
        __syncthreads();
        if (j + 2 < 8) {
            uint32_t stSlot = wBase + (uint32_t)(((gch + 2) % 3) * (WSLOTW * 4));
            stage_w<128, 256>(stSlot, g_W3t, j + 2, tid);
            CP_COMMIT();
        }
        uint32_t bRow = wBase + (uint32_t)((gch % 3) * (WSLOTW * 4)) + rowoff3;
        gemm32<1>(acc3, sbyte, 512, 4 * j, bRow, lane);
    }
    __syncthreads();                      // all H2/W reads done

    // ---- output epilogue: f32 scratch (stride 132 over dead H/W) ----
    float* fH = (float*)smw;
#pragma unroll
    for (int nt = 0; nt < 2; nt++) {
        int c = n3 + nt * 8 + 2 * t;
        float bb0 = __ldg(b3 + c);
        float bb1 = __ldg(b3 + c + 1);
#pragma unroll
        for (int mt = 0; mt < 4; mt++) {
            int r = mt * 16 + g;
            *(float2*)(fH + r * 132 + c) =
                make_float2(acc3[mt][nt][0] + bb0, acc3[mt][nt][1] + bb1);
            *(float2*)(fH + (r + 8) * 132 + c) =
                make_float2(acc3[mt][nt][2] + bb0, acc3[mt][nt][3] + bb1);
        }
    }
    __syncthreads();
#pragma unroll
    for (int it = 0; it < 8; it++) {
        int task = tid + it * THREADS;
        int row = task >> 5, c4 = task & 31;
        *(float4*)(out + (e0 + row) * 128 + c4 * 4) =
            *(const float4*)(fH + row * 132 + c4 * 4);
    }
}

extern "C" void kernel_launch(void* const* d_in, const int* in_sizes, int n_in,
                              void* d_out, int out_size) {
    const float* src  = (const float*)d_in[0];
    const float* dstp = (const float*)d_in[1];
    const float* ea   = (const float*)d_in[2];
    const float* u    = (const float*)d_in[3];
    const void*  bat  = (const void*)d_in[4];
    const float* W1   = (const float*)d_in[5];
    const float* b1   = (const float*)d_in[6];
    const float* W2   = (const float*)d_in[7];
    const float* b2   = (const float*)d_in[8];
    const float* W3   = (const float*)d_in[9];
    const float* b3   = (const float*)d_in[10];
    float* out = (float*)d_out;

    cudaFuncSetAttribute(edge_mlp_v11,
                         cudaFuncAttributeMaxDynamicSharedMemorySize, SMEM_BYTES);

    __half *w1t, *w2t, *w3t;
    cudaGetSymbolAddress((void**)&w1t, g_W1t);
    cudaGetSymbolAddress((void**)&w2t, g_W2t);
    cudaGetSymbolAddress((void**)&w3t, g_W3t);
    dim3 blk(32, 8);
    prep_w<<<dim3(16, 8), blk>>>(W1, w1t, 512, 256);
    prep_w<<<dim3(8, 8),  blk>>>(W2, w2t, 256, 256);
    prep_w<<<dim3(8, 4),  blk>>>(W3, w3t, 256, 128);

    const int n_edges = in_sizes[4];
    const int grid = n_edges / CTA_M;   // 6250
    edge_mlp_v11<<<grid, THREADS, SMEM_BYTES>>>(src, dstp, ea, u, bat,
                                                b1, b2, b3, out);
}

// round 12
// speedup vs baseline: 1.0690x; 1.0690x over previous
#include <cuda_runtime.h>
#include <cuda_fp16.h>
#include <cstdint>

#define THREADS 512
#define CTA_M   64
#define HROW    128                     // H row stride (words); 64 rows at offset 0
#define XSLOTW  2048                    // X slot: 64 rows x 32 words (one 64-K chunk)
#define WOFFW   8192
#define WSLOTW  8192                    // W slot: 256 rows x 32 words
#define WSLOTB  (WSLOTW * 4)
#define SMEM_WORDS (WOFFW + 2 * WSLOTW) // 24576
#define SMEM_BYTES (SMEM_WORDS * 4)     // 98304 (2 CTAs/SM)

// pre-transposed fp16 weights, natural K-major: Wt[n][k]
__device__ __half g_W1t[256 * 512];
__device__ __half g_W2t[256 * 256];
__device__ __half g_W3t[128 * 256];

__device__ __forceinline__ uint32_t smem_u32(const void* p) {
    uint32_t a;
    asm("{ .reg .u64 t; cvta.to.shared.u64 t, %1; cvt.u32.u64 %0, t; }" : "=r"(a) : "l"(p));
    return a;
}
__device__ __forceinline__ float softplus_f(float x) {
    return (x > 20.0f) ? x : __logf(1.0f + __expf(x));
}
__device__ __forceinline__ uint32_t pack_h2(float lo, float hi) {
    __half2 h = __halves2half2(__float2half_rn(lo), __float2half_rn(hi));
    return *(uint32_t*)&h;
}
__device__ __forceinline__ void mma16(float* c, uint32_t a0, uint32_t a1,
                                      uint32_t a2, uint32_t a3,
                                      uint32_t b0, uint32_t b1) {
    asm volatile(
        "mma.sync.aligned.m16n8k16.row.col.f32.f16.f16.f32 "
        "{%0,%1,%2,%3}, {%4,%5,%6,%7}, {%8,%9}, {%0,%1,%2,%3};\n"
        : "+f"(c[0]), "+f"(c[1]), "+f"(c[2]), "+f"(c[3])
        : "r"(a0), "r"(a1), "r"(a2), "r"(a3), "r"(b0), "r"(b1));
}
__device__ __forceinline__ void ldsm4(uint32_t* r, uint32_t addr) {
    asm volatile("ldmatrix.sync.aligned.m8n8.x4.shared.b16 {%0,%1,%2,%3}, [%4];"
        : "=r"(r[0]), "=r"(r[1]), "=r"(r[2]), "=r"(r[3]) : "r"(addr));
}
__device__ __forceinline__ void cp16(uint32_t dst, const void* src) {
    asm volatile("cp.async.cg.shared.global [%0], [%1], 16;" :: "r"(dst), "l"(src) : "memory");
}
#define CP_COMMIT() asm volatile("cp.async.commit_group;" ::: "memory")
#define CP_WAIT1()  asm volatile("cp.async.wait_group 1;" ::: "memory")

// ---- GEMM over one 64-K chunk via ldmatrix. Warp tile 32M x (NTP*16)N.
// A rows at aBase (already offset by warp's m0), row stride arowB bytes,
// unit base aub (=8*kc for H). B at bBase (lane-resolved n row base, 128B rows).
template <int NTP>
__device__ __forceinline__ void gemm64(float acc[2][2 * NTP][4],
                                       uint32_t aBase, int arowB, int aub,
                                       uint32_t bBase, int lane) {
    int rw = lane & 7;
    int duA = (lane >> 4) & 1;
    int duB = (lane >> 3) & 1;
    uint32_t aL = aBase + (uint32_t)((((lane >> 3) & 1) * 8 + rw) * arowB);
#pragma unroll
    for (int gi = 0; gi < 4; gi++) {
        uint32_t uA = (uint32_t)((aub + ((2 * gi + duA))) ^ rw) << 4;
        uint32_t a[2][4];
#pragma unroll
        for (int mt = 0; mt < 2; mt++)
            ldsm4(a[mt], aL + mt * 16 * arowB + uA);
        uint32_t uB = (uint32_t)((2 * gi + duB) ^ rw) << 4;
#pragma unroll
        for (int ntp = 0; ntp < NTP; ntp++) {
            uint32_t b[4];
            ldsm4(b, bBase + ntp * (16 * 128) + uB);
#pragma unroll
            for (int mt = 0; mt < 2; mt++) {
                mma16(acc[mt][2 * ntp],     a[mt][0], a[mt][1], a[mt][2], a[mt][3], b[0], b[1]);
                mma16(acc[mt][2 * ntp + 1], a[mt][0], a[mt][1], a[mt][2], a[mt][3], b[2], b[3]);
            }
        }
    }
}

// ---- X staging: one 64-K chunk for 64 edges (first 256 threads) ----
__device__ __forceinline__ void stage_x(uint32_t* x, int kc, long e0,
                                        const float* __restrict__ src,
                                        const float* __restrict__ dstp,
                                        const float* __restrict__ ea,
                                        const float* __restrict__ u,
                                        const void* __restrict__ batch, int b64, int tid) {
    if (tid >= 256) return;
    int row = tid >> 2, q = tid & 3;
    int k0 = kc * 64, seg = k0 >> 7, off = (k0 & 127) + q * 16;
    const float* p;
    if (seg == 0)      p = src  + (e0 + row) * 128;
    else if (seg == 1) p = dstp + (e0 + row) * 128;
    else if (seg == 2) p = ea   + (e0 + row) * 128;
    else {
        long bi = b64 ? (long)((const long long*)batch)[e0 + row]
                      : (long)((const int*)batch)[e0 + row];
        p = u + bi * 128;
    }
    float4 f0 = *(const float4*)(p + off);
    float4 f1 = *(const float4*)(p + off + 4);
    float4 f2 = *(const float4*)(p + off + 8);
    float4 f3 = *(const float4*)(p + off + 12);
    uint4 o1 = make_uint4(pack_h2(f0.x, f0.y), pack_h2(f0.z, f0.w),
                          pack_h2(f1.x, f1.y), pack_h2(f1.z, f1.w));
    uint4 o2 = make_uint4(pack_h2(f2.x, f2.y), pack_h2(f2.z, f2.w),
                          pack_h2(f3.x, f3.y), pack_h2(f3.z, f3.w));
    int rm = row & 7;
    *(uint4*)(x + row * 32 + (((2 * q) ^ rm) << 2)) = o1;
    *(uint4*)(x + row * 32 + (((2 * q + 1) ^ rm) << 2)) = o2;
}

// ---- W staging: 64-K chunk via cp.async (16B units), swizzled dst ----
template <int NROWS, int KFULL>
__device__ __forceinline__ void stage_w(uint32_t wbase_byte, const __half* __restrict__ Wt,
                                        int kc, int tid) {
#pragma unroll
    for (int it = 0; it < (NROWS * 8) / THREADS; it++) {
        int task = tid + it * THREADS;
        int row = task >> 3, q = task & 7;
        uint32_t dst = wbase_byte + (row * 32 + ((q ^ (row & 7)) << 2)) * 4;
        cp16(dst, Wt + (long)row * KFULL + kc * 64 + q * 8);
    }
}

// ---- epilogue layers 1/2: bias + softplus -> half2 into H ----
template <int NT>
__device__ __forceinline__ void epi_h(float acc[2][NT][4], uint32_t* smw,
                                      const float* __restrict__ bias,
                                      int m0, int n0, int g, int t) {
#pragma unroll
    for (int nt = 0; nt < NT; nt++) {
        int c = n0 + nt * 8 + 2 * t;
        float bb0 = __ldg(bias + c);
        float bb1 = __ldg(bias + c + 1);
        int uu = (n0 >> 3) + nt;
        int w = ((uu ^ g) << 2) + t;     // (r&7)==g for rows below
#pragma unroll
        for (int mt = 0; mt < 2; mt++) {
            int r = m0 + mt * 16 + g;
            smw[r * HROW + w] =
                pack_h2(softplus_f(acc[mt][nt][0] + bb0), softplus_f(acc[mt][nt][1] + bb1));
            smw[(r + 8) * HROW + w] =
                pack_h2(softplus_f(acc[mt][nt][2] + bb0), softplus_f(acc[mt][nt][3] + bb1));
        }
    }
}

// ---- prepass: W [K][N] -> Wt [N][K] fp16 ----
__global__ void prep_w(const float* __restrict__ W, __half* __restrict__ Wt,
                       int K, int N) {
    __shared__ float tile[32][33];
    int kb = blockIdx.x * 32, nb = blockIdx.y * 32;
    int tx = threadIdx.x, ty = threadIdx.y;
    for (int i = ty; i < 32; i += 8)
        tile[i][tx] = W[(long)(kb + i) * N + nb + tx];
    __syncthreads();
    for (int i = ty; i < 32; i += 8)
        Wt[(long)(nb + i) * K + kb + tx] = __float2half_rn(tile[tx][i]);
}

__global__ void __launch_bounds__(THREADS, 2)
edge_mlp_v12(const float* __restrict__ src, const float* __restrict__ dstp,
             const float* __restrict__ ea, const float* __restrict__ u,
             const void* __restrict__ batch,
             const float* __restrict__ b1, const float* __restrict__ b2,
             const float* __restrict__ b3,
             float* __restrict__ out) {
    extern __shared__ uint32_t smw[];
    uint32_t sbyte = smem_u32(smw);

    int tid = threadIdx.x;
    int wid = tid >> 5;                  // 0..15
    int lane = tid & 31;
    int g = lane >> 2;
    int t = lane & 3;
    int m0 = (wid & 1) * 32;             // 2 warps over M
    int n0 = (wid >> 1) * 32;            // 8 warps over N (layers 1/2)
    int n3 = (wid >> 1) * 16;            // layer 3
    long e0 = (long)blockIdx.x * CTA_M;

    uint32_t wb[2] = { sbyte + WOFFW * 4, sbyte + WOFFW * 4 + WSLOTB };
    // lane-resolved B row bases (row = n + (lane>>4)*8 + (lane&7), 128B rows)
    uint32_t bL12 = sbyte + WOFFW * 4 + (uint32_t)((n0 + ((lane >> 4) & 1) * 8 + (lane & 7)) * 128);
    uint32_t bL3  = sbyte + WOFFW * 4 + (uint32_t)((n3 + ((lane >> 4) & 1) * 8 + (lane & 7)) * 128);

    __shared__ int b64s;
    if (tid == 0) {
        const long long* p = (const long long*)batch;
        int f = 1;
        for (int i = 0; i < 16; i++) { long long v = p[i]; if (v < 0 || v >= 64) f = 0; }
        b64s = f;
    }
    __syncthreads();
    int b64 = b64s;

    float acc[2][4][4];
#pragma unroll
    for (int a = 0; a < 2; a++)
#pragma unroll
        for (int b = 0; b < 4; b++)
#pragma unroll
            for (int c = 0; c < 4; c++) acc[a][b][c] = 0.0f;

    // ============== Layer 1: K=512 (8 chunks of 64), N=256 ================
    stage_x(smw, 0, e0, src, dstp, ea, u, batch, b64, tid);
    stage_w<256, 512>(wb[0], g_W1t, 0, tid);
    CP_COMMIT();
    stage_x(smw + XSLOTW, 1, e0, src, dstp, ea, u, batch, b64, tid);
    stage_w<256, 512>(wb[1], g_W1t, 1, tid);
    CP_COMMIT();
#pragma unroll 1
    for (int kc = 0; kc < 8; kc++) {
        int s = kc & 1;
        CP_WAIT1();
        __syncthreads();
        gemm64<2>(acc, sbyte + s * (XSLOTW * 4) + m0 * 128, 128, 0,
                  bL12 + s * WSLOTB, lane);
        __syncthreads();
        if (kc < 6) {
            stage_x(smw + s * XSLOTW, kc + 2, e0, src, dstp, ea, u, batch, b64, tid);
            stage_w<256, 512>(wb[s], g_W1t, kc + 2, tid);
        } else {
            stage_w<256, 256>(wb[s], g_W2t, kc - 6, tid);   // prefetch W2
        }
        CP_COMMIT();
    }
    epi_h<4>(acc, smw, b1, m0, n0, g, t);
    __syncthreads();                      // publish H1

    // ============== Layer 2: K=256 (4 chunks), N=256, A = H ===============
#pragma unroll
    for (int a = 0; a < 2; a++)
#pragma unroll
        for (int b = 0; b < 4; b++)
#pragma unroll
            for (int c = 0; c < 4; c++) acc[a][b][c] = 0.0f;
#pragma unroll 1
    for (int kc = 0; kc < 4; kc++) {
        int s = kc & 1;
        CP_WAIT1();
        __syncthreads();
        gemm64<2>(acc, sbyte + m0 * 512, 512, 8 * kc, bL12 + s * WSLOTB, lane);
        __syncthreads();
        if (kc < 2) stage_w<256, 256>(wb[s], g_W2t, kc + 2, tid);
        else        stage_w<128, 256>(wb[s], g_W3t, kc - 2, tid);   // prefetch W3
        CP_COMMIT();
    }
    epi_h<4>(acc, smw, b2, m0, n0, g, t);
    __syncthreads();                      // publish H2

    // ============== Layer 3: K=256 (4 chunks), N=128, A = H ===============
    float acc3[2][2][4];
#pragma unroll
    for (int a = 0; a < 2; a++)
#pragma unroll
        for (int b = 0; b < 2; b++)
#pragma unroll
            for (int c = 0; c < 4; c++) acc3[a][b][c] = 0.0f;
#pragma unroll 1
    for (int kc = 0; kc < 4; kc++) {
        int s = kc & 1;
        CP_WAIT1();
        __syncthreads();
        gemm64<1>(acc3, sbyte + m0 * 512, 512, 8 * kc, bL3 + s * WSLOTB, lane);
        __syncthreads();
        if (kc < 2) stage_w<128, 256>(wb[s], g_W3t, kc + 2, tid);
        CP_COMMIT();
    }

    // ---- output epilogue: f32 scratch (stride 132 over dead H/W) ----
    float* fH = (float*)smw;
#pragma unroll
    for (int nt = 0; nt < 2; nt++) {
        int c = n3 + nt * 8 + 2 * t;
        float bb0 = __ldg(b3 + c);
        float bb1 = __ldg(b3 + c + 1);
#pragma unroll
        for (int mt = 0; mt < 2; mt++) {
            int r = m0 + mt * 16 + g;
            *(float2*)(fH + r * 132 + c) =
                make_float2(acc3[mt][nt][0] + bb0, acc3[mt][nt][1] + bb1);
            *(float2*)(fH + (r + 8) * 132 + c) =
                make_float2(acc3[mt][nt][2] + bb0, acc3[mt][nt][3] + bb1);
        }
    }
    __syncthreads();
#pragma unroll
    for (int it = 0; it < 4; it++) {
        int task = tid + it * THREADS;    // 64 rows x 32 float4 = 2048
        int row = task >> 5, c4 = task & 31;
        *(float4*)(out + (e0 + row) * 128 + c4 * 4) =
            *(const float4*)(fH + row * 132 + c4 * 4);
    }
}

extern "C" void kernel_launch(void* const* d_in, const int* in_sizes, int n_in,
                              void* d_out, int out_size) {
    const float* src  = (const float*)d_in[0];
    const float* dstp = (const float*)d_in[1];
    const float* ea   = (const float*)d_in[2];
    const float* u    = (const float*)d_in[3];
    const void*  bat  = (const void*)d_in[4];
    const float* W1   = (const float*)d_in[5];
    const float* b1   = (const float*)d_in[6];
    const float* W2   = (const float*)d_in[7];
    const float* b2   = (const float*)d_in[8];
    const float* W3   = (const float*)d_in[9];
    const float* b3   = (const float*)d_in[10];
    float* out = (float*)d_out;

    cudaFuncSetAttribute(edge_mlp_v12,
                         cudaFuncAttributeMaxDynamicSharedMemorySize, SMEM_BYTES);

    __half *w1t, *w2t, *w3t;
    cudaGetSymbolAddress((void**)&w1t, g_W1t);
    cudaGetSymbolAddress((void**)&w2t, g_W2t);
    cudaGetSymbolAddress((void**)&w3t, g_W3t);
    dim3 blk(32, 8);
    prep_w<<<dim3(16, 8), blk>>>(W1, w1t, 512, 256);
    prep_w<<<dim3(8, 8),  blk>>>(W2, w2t, 256, 256);
    prep_w<<<dim3(8, 4),  blk>>>(W3, w3t, 256, 128);

    const int n_edges = in_sizes[4];
    const int grid = n_edges / CTA_M;   // 6250
    edge_mlp_v12<<<grid, THREADS, SMEM_BYTES>>>(src, dstp, ea, u, bat,
                                                b1, b2, b3, out);
}

// round 13
// speedup vs baseline: 1.1630x; 1.0879x over previous
#include <cuda_runtime.h>
#include <cuda_fp16.h>
#include <cstdint>

#define THREADS 256
#define CTA_M   64
#define HROW    128                     // H row stride (words); 64 rows at offset 0
#define XSLOTW  2048                    // X slot: 64 rows x 32 words (one 64-K chunk)
#define WOFFW   8192
#define WSLOTW  8192                    // W slot: 256 rows x 32 words
#define WSLOTB  (WSLOTW * 4)
#define SMEM_WORDS (WOFFW + 2 * WSLOTW) // 24576
#define SMEM_BYTES (SMEM_WORDS * 4)     // 98304 (2 CTAs/SM)

// pre-transposed fp16 weights, natural K-major: Wt[n][k]
__device__ __half g_W1t[256 * 512];
__device__ __half g_W2t[256 * 256];
__device__ __half g_W3t[128 * 256];

__device__ __forceinline__ uint32_t smem_u32(const void* p) {
    uint32_t a;
    asm("{ .reg .u64 t; cvta.to.shared.u64 t, %1; cvt.u32.u64 %0, t; }" : "=r"(a) : "l"(p));
    return a;
}
__device__ __forceinline__ float softplus_f(float x) {
    return (x > 20.0f) ? x : __logf(1.0f + __expf(x));
}
__device__ __forceinline__ uint32_t pack_h2(float lo, float hi) {
    __half2 h = __halves2half2(__float2half_rn(lo), __float2half_rn(hi));
    return *(uint32_t*)&h;
}
__device__ __forceinline__ void mma16(float* c, uint32_t a0, uint32_t a1,
                                      uint32_t a2, uint32_t a3,
                                      uint32_t b0, uint32_t b1) {
    asm volatile(
        "mma.sync.aligned.m16n8k16.row.col.f32.f16.f16.f32 "
        "{%0,%1,%2,%3}, {%4,%5,%6,%7}, {%8,%9}, {%0,%1,%2,%3};\n"
        : "+f"(c[0]), "+f"(c[1]), "+f"(c[2]), "+f"(c[3])
        : "r"(a0), "r"(a1), "r"(a2), "r"(a3), "r"(b0), "r"(b1));
}
__device__ __forceinline__ void ldsm4(uint32_t* r, uint32_t addr) {
    asm volatile("ldmatrix.sync.aligned.m8n8.x4.shared.b16 {%0,%1,%2,%3}, [%4];"
        : "=r"(r[0]), "=r"(r[1]), "=r"(r[2]), "=r"(r[3]) : "r"(addr));
}
__device__ __forceinline__ void cp16(uint32_t dst, const void* src) {
    asm volatile("cp.async.cg.shared.global [%0], [%1], 16;" :: "r"(dst), "l"(src) : "memory");
}
#define CP_COMMIT() asm volatile("cp.async.commit_group;" ::: "memory")
#define CP_WAIT1()  asm volatile("cp.async.wait_group 1;" ::: "memory")

// ---- GEMM over one 64-K chunk via ldmatrix (R9, unchanged) ----
template <int NTP>
__device__ __forceinline__ void gemm64(float acc[4][2 * NTP][4],
                                       uint32_t aBase, int arowB, int aub,
                                       uint32_t bBase, int lane) {
    int rw = lane & 7;
    int duA = (lane >> 4) & 1;
    int duB = (lane >> 3) & 1;
    uint32_t aL = aBase + (uint32_t)((((lane >> 3) & 1) * 8 + rw) * arowB);
#pragma unroll
    for (int gi = 0; gi < 4; gi++) {
        uint32_t uA = (uint32_t)(aub + ((2 * gi + duA) ^ rw)) << 4;
        uint32_t a[4][4];
#pragma unroll
        for (int mt = 0; mt < 4; mt++)
            ldsm4(a[mt], aL + mt * 16 * arowB + uA);
        uint32_t uB = (uint32_t)((2 * gi + duB) ^ rw) << 4;
#pragma unroll
        for (int ntp = 0; ntp < NTP; ntp++) {
            uint32_t b[4];
            ldsm4(b, bBase + ntp * (16 * 128) + uB);
#pragma unroll
            for (int mt = 0; mt < 4; mt++) {
                mma16(acc[mt][2 * ntp],     a[mt][0], a[mt][1], a[mt][2], a[mt][3], b[0], b[1]);
                mma16(acc[mt][2 * ntp + 1], a[mt][0], a[mt][1], a[mt][2], a[mt][3], b[2], b[3]);
            }
        }
    }
}

// ---- X staging split: LDG (hoisted above gemm) / STS (R10-verified) ----
__device__ __forceinline__ void x_ldg(float4 xv[4], const float* p, int kc, int tid) {
    int q = tid & 3;
    int off = ((kc * 64) & 127) + q * 16;
    xv[0] = *(const float4*)(p + off);
    xv[1] = *(const float4*)(p + off + 4);
    xv[2] = *(const float4*)(p + off + 8);
    xv[3] = *(const float4*)(p + off + 12);
}
__device__ __forceinline__ void x_sts(uint32_t* x, const float4 xv[4], int tid) {
    int row = tid >> 2, q = tid & 3;
    uint4 o1 = make_uint4(pack_h2(xv[0].x, xv[0].y), pack_h2(xv[0].z, xv[0].w),
                          pack_h2(xv[1].x, xv[1].y), pack_h2(xv[1].z, xv[1].w));
    uint4 o2 = make_uint4(pack_h2(xv[2].x, xv[2].y), pack_h2(xv[2].z, xv[2].w),
                          pack_h2(xv[3].x, xv[3].y), pack_h2(xv[3].z, xv[3].w));
    int rm = row & 7;
    *(uint4*)(x + row * 32 + (((2 * q) ^ rm) << 2)) = o1;
    *(uint4*)(x + row * 32 + (((2 * q + 1) ^ rm) << 2)) = o2;
}

// ---- W staging: 64-K chunk via cp.async (16B units), swizzled dst ----
template <int NROWS, int KFULL>
__device__ __forceinline__ void stage_w(uint32_t wbase_byte, const __half* __restrict__ Wt,
                                        int kc, int tid) {
#pragma unroll
    for (int it = 0; it < (NROWS * 8) / THREADS; it++) {
        int task = tid + it * THREADS;
        int row = task >> 3, q = task & 7;
        uint32_t dst = wbase_byte + (row * 32 + ((q ^ (row & 7)) << 2)) * 4;
        cp16(dst, Wt + (long)row * KFULL + kc * 64 + q * 8);
    }
}

// ---- epilogue layers 1/2: bias + softplus -> half2 into H (R9) ----
template <int NT>
__device__ __forceinline__ void epi_h(float acc[4][NT][4], uint32_t* smw,
                                      const float* __restrict__ bias,
                                      int n0, int g, int t) {
#pragma unroll
    for (int nt = 0; nt < NT; nt++) {
        int c = n0 + nt * 8 + 2 * t;
        float bb0 = __ldg(bias + c);
        float bb1 = __ldg(bias + c + 1);
        int uu = (n0 >> 3) + nt;
        int w = ((uu ^ g) << 2) + t;
#pragma unroll
        for (int mt = 0; mt < 4; mt++) {
            int r = mt * 16 + g;
            smw[r * HROW + w] =
                pack_h2(softplus_f(acc[mt][nt][0] + bb0), softplus_f(acc[mt][nt][1] + bb1));
            smw[(r + 8) * HROW + w] =
                pack_h2(softplus_f(acc[mt][nt][2] + bb0), softplus_f(acc[mt][nt][3] + bb1));
        }
    }
}

// ---- prepass: W [K][N] -> Wt [N][K] fp16 ----
__global__ void prep_w(const float* __restrict__ W, __half* __restrict__ Wt,
                       int K, int N) {
    __shared__ float tile[32][33];
    int kb = blockIdx.x * 32, nb = blockIdx.y * 32;
    int tx = threadIdx.x, ty = threadIdx.y;
    for (int i = ty; i < 32; i += 8)
        tile[i][tx] = W[(long)(kb + i) * N + nb + tx];
    __syncthreads();
    for (int i = ty; i < 32; i += 8)
        Wt[(long)(nb + i) * K + kb + tx] = __float2half_rn(tile[tx][i]);
}

__global__ void __launch_bounds__(THREADS, 2)
edge_mlp_v13(const float* __restrict__ src, const float* __restrict__ dstp,
             const float* __restrict__ ea, const float* __restrict__ u,
             const void* __restrict__ batch,
             const float* __restrict__ b1, const float* __restrict__ b2,
             const float* __restrict__ b3,
             float* __restrict__ out) {
    extern __shared__ uint32_t smw[];
    uint32_t sbyte = smem_u32(smw);

    int tid = threadIdx.x;
    int wid = tid >> 5;
    int lane = tid & 31;
    int g = lane >> 2;
    int t = lane & 3;
    int n0 = wid * 32;
    int n3 = wid * 16;
    long e0 = (long)blockIdx.x * CTA_M;

    uint32_t wb[2] = { sbyte + WOFFW * 4, sbyte + WOFFW * 4 + WSLOTB };
    uint32_t bL12 = sbyte + WOFFW * 4 + (uint32_t)((n0 + ((lane >> 4) & 1) * 8 + (lane & 7)) * 128);
    uint32_t bL3  = sbyte + WOFFW * 4 + (uint32_t)((n3 + ((lane >> 4) & 1) * 8 + (lane & 7)) * 128);

    __shared__ int b64s;
    if (tid == 0) {
        const long long* p = (const long long*)batch;
        int f = 1;
        for (int i = 0; i < 16; i++) { long long v = p[i]; if (v < 0 || v >= 64) f = 0; }
        b64s = f;
    }
    __syncthreads();
    int b64 = b64s;

    // ---- per-thread X source pointers, gather index resolved ONCE ----
    int xrow = tid >> 2;
    const float* pseg0 = src  + (e0 + xrow) * 128;
    const float* pseg1 = dstp + (e0 + xrow) * 128;
    const float* pseg2 = ea   + (e0 + xrow) * 128;
    long bi = b64 ? (long)((const long long*)batch)[e0 + xrow]
                  : (long)((const int*)batch)[e0 + xrow];
    const float* pseg3 = u + bi * 128;

    float acc[4][4][4];
#pragma unroll
    for (int a = 0; a < 4; a++)
#pragma unroll
        for (int b = 0; b < 4; b++)
#pragma unroll
            for (int c = 0; c < 4; c++) acc[a][b][c] = 0.0f;

    // ============== Layer 1: K=512 (8 chunks of 64), N=256 ================
    {
        float4 xv[4];
        x_ldg(xv, pseg0, 0, tid);
        x_sts(smw, xv, tid);
        stage_w<256, 512>(wb[0], g_W1t, 0, tid);
        CP_COMMIT();
        x_ldg(xv, pseg0, 1, tid);
        x_sts(smw + XSLOTW, xv, tid);
        stage_w<256, 512>(wb[1], g_W1t, 1, tid);
        CP_COMMIT();
    }
#pragma unroll 1
    for (int kc = 0; kc < 8; kc++) {
        int s = kc & 1;
        CP_WAIT1();
        __syncthreads();
        float4 xv[4];
        bool pfx = (kc < 6);
        if (pfx) {
            int kn = kc + 2;
            int seg = kn >> 1;
            const float* p = (seg == 0) ? pseg0 : (seg == 1) ? pseg1
                           : (seg == 2) ? pseg2 : pseg3;
            x_ldg(xv, p, kn, tid);            // LDG latency hides under gemm
        }
        gemm64<2>(acc, sbyte + s * (XSLOTW * 4), 128, 0, bL12 + s * WSLOTB, lane);
        __syncthreads();
        if (pfx) {
            x_sts(smw + s * XSLOTW, xv, tid);
            stage_w<256, 512>(wb[s], g_W1t, kc + 2, tid);
        } else {
            stage_w<256, 256>(wb[s], g_W2t, kc - 6, tid);   // prefetch W2
        }
        CP_COMMIT();
    }
    epi_h<4>(acc, smw, b1, n0, g, t);
    __syncthreads();                      // publish H1

    // ============== Layer 2: K=256 (4 chunks), N=256, A = H ===============
#pragma unroll
    for (int a = 0; a < 4; a++)
#pragma unroll
        for (int b = 0; b < 4; b++)
#pragma unroll
            for (int c = 0; c < 4; c++) acc[a][b][c] = 0.0f;
#pragma unroll 1
    for (int kc = 0; kc < 4; kc++) {
        int s = kc & 1;
        CP_WAIT1();
        __syncthreads();
        gemm64<2>(acc, sbyte, 512, 8 * kc, bL12 + s * WSLOTB, lane);
        __syncthreads();
        if (kc < 2) stage_w<256, 256>(wb[s], g_W2t, kc + 2, tid);
        else        stage_w<128, 256>(wb[s], g_W3t, kc - 2, tid);   // prefetch W3
        CP_COMMIT();
    }
    epi_h<4>(acc, smw, b2, n0, g, t);
    __syncthreads();                      // publish H2

    // ============== Layer 3: K=256 (4 chunks), N=128, A = H ===============
    float acc3[4][2][4];
#pragma unroll
    for (int a = 0; a < 4; a++)
#pragma unroll
        for (int b = 0; b < 2; b++)
#pragma unroll
            for (int c = 0; c < 4; c++) acc3[a][b][c] = 0.0f;
#pragma unroll 1
    for (int kc = 0; kc < 4; kc++) {
        int s = kc & 1;
        CP_WAIT1();
        __syncthreads();
        gemm64<1>(acc3, sbyte, 512, 8 * kc, bL3 + s * WSLOTB, lane);
        __syncthreads();
        if (kc < 2) stage_w<128, 256>(wb[s], g_W3t, kc + 2, tid);
        CP_COMMIT();
    }

    // ---- output epilogue: f32 scratch (stride 132 over dead H/W) ----
    float* fH = (float*)smw;
#pragma unroll
    for (int nt = 0; nt < 2; nt++) {
        int c = n3 + nt * 8 + 2 * t;
        float bb0 = __ldg(b3 + c);
        float bb1 = __ldg(b3 + c + 1);
#pragma unroll
        for (int mt = 0; mt < 4; mt++) {
            int r = mt * 16 + g;
            *(float2*)(fH + r * 132 + c) =
                make_float2(acc3[mt][nt][0] + bb0, acc3[mt][nt][1] + bb1);
            *(float2*)(fH + (r + 8) * 132 + c) =
                make_float2(acc3[mt][nt][2] + bb0, acc3[mt][nt][3] + bb1);
        }
    }
    __syncthreads();
#pragma unroll
    for (int it = 0; it < 8; it++) {
        int task = tid + it * THREADS;
        int row = task >> 5, c4 = task & 31;
        *(float4*)(out + (e0 + row) * 128 + c4 * 4) =
            *(const float4*)(fH + row * 132 + c4 * 4);
    }
}

extern "C" void kernel_launch(void* const* d_in, const int* in_sizes, int n_in,
                              void* d_out, int out_size) {
    const float* src  = (const float*)d_in[0];
    const float* dstp = (const float*)d_in[1];
    const float* ea   = (const float*)d_in[2];
    const float* u    = (const float*)d_in[3];
    const void*  bat  = (const void*)d_in[4];
    const float* W1   = (const float*)d_in[5];
    const float* b1   = (const float*)d_in[6];
    const float* W2   = (const float*)d_in[7];
    const float* b2   = (const float*)d_in[8];
    const float* W3   = (const float*)d_in[9];
    const float* b3   = (const float*)d_in[10];
    float* out = (float*)d_out;

    cudaFuncSetAttribute(edge_mlp_v13,
                         cudaFuncAttributeMaxDynamicSharedMemorySize, SMEM_BYTES);

    __half *w1t, *w2t, *w3t;
    cudaGetSymbolAddress((void**)&w1t, g_W1t);
    cudaGetSymbolAddress((void**)&w2t, g_W2t);
    cudaGetSymbolAddress((void**)&w3t, g_W3t);
    dim3 blk(32, 8);
    prep_w<<<dim3(16, 8), blk>>>(W1, w1t, 512, 256);
    prep_w<<<dim3(8, 8),  blk>>>(W2, w2t, 256, 256);
    prep_w<<<dim3(8, 4),  blk>>>(W3, w3t, 256, 128);

    const int n_edges = in_sizes[4];
    const int grid = n_edges / CTA_M;   // 6250
    edge_mlp_v13<<<grid, THREADS, SMEM_BYTES>>>(src, dstp, ea, u, bat,
                                                b1, b2, b3, out);
}